// round 1
// baseline (speedup 1.0000x reference)
#include <cuda_runtime.h>

#define HIDDEN 1024
#define HEADS 16
#define HD 64
#define RANK 16
#define BSZ 4
#define SEQ 2048
#define BH (BSZ*HEADS)          // 64
#define NPROJ 3
#define LORA_SCALE (1.0f/16.0f)
#define SM_SCALE 0.125f          // 1/sqrt(64)

// Scratch (no allocations allowed): effective weights + projected Q,K,V in [p][bh][s][d] layout.
__device__ float g_Weff[(size_t)NPROJ*HIDDEN*HIDDEN];                 // 12 MB
__device__ float g_QKV[(size_t)NPROJ*BH*SEQ*HD];                      // ~100 MB

// ---------------------------------------------------------------------------
// Kernel 1: W_eff = W + (1/16) * B @ A   (folds LoRA into the dense weight)
// ---------------------------------------------------------------------------
__global__ void weff_kernel(const float* __restrict__ Wq, const float* __restrict__ Aq, const float* __restrict__ Bq,
                            const float* __restrict__ Wk, const float* __restrict__ Ak, const float* __restrict__ Bk,
                            const float* __restrict__ Wv, const float* __restrict__ Av, const float* __restrict__ Bv) {
    int idx = blockIdx.x * blockDim.x + threadIdx.x;
    if (idx >= NPROJ*HIDDEN*HIDDEN) return;
    int p  = idx >> 20;                  // HIDDEN*HIDDEN = 2^20
    int nk = idx & ((1 << 20) - 1);
    int n  = nk >> 10;
    int k  = nk & 1023;
    const float* W = (p == 0) ? Wq : ((p == 1) ? Wk : Wv);
    const float* A = (p == 0) ? Aq : ((p == 1) ? Ak : Av);
    const float* B = (p == 0) ? Bq : ((p == 1) ? Bk : Bv);
    float acc = 0.f;
#pragma unroll
    for (int r = 0; r < RANK; r++) acc += B[n*RANK + r] * A[r*HIDDEN + k];
    g_Weff[idx] = W[nk] + LORA_SCALE * acc;
}

// ---------------------------------------------------------------------------
// Kernel 2: QKV GEMM.  C[m][n] = sum_k X[m][k] * Weff[n][k] + bias[n]
// M = 8192, N = 3072 (q|k|v fused), K = 1024.  128x128x16 tiles, 8x8/thread.
// Epilogue scatters into g_QKV[p][b*16+h][s][d].
// ---------------------------------------------------------------------------
__global__ __launch_bounds__(256) void qkv_gemm(const float* __restrict__ X,
                                                const float* __restrict__ bq,
                                                const float* __restrict__ bk,
                                                const float* __restrict__ bv) {
    __shared__ __align__(16) float sA[16][128];
    __shared__ __align__(16) float sB[16][128];
    int tid = threadIdx.x;
    int m0 = blockIdx.y * 128;
    int n0 = blockIdx.x * 128;
    int ty = tid >> 4, tx = tid & 15;
    float acc[8][8];
#pragma unroll
    for (int i = 0; i < 8; i++)
#pragma unroll
        for (int j = 0; j < 8; j++) acc[i][j] = 0.f;

    for (int k0 = 0; k0 < HIDDEN; k0 += 16) {
#pragma unroll
        for (int it = 0; it < 2; it++) {
            int f   = tid + it * 256;          // 0..511
            int row = f >> 2;
            int c4  = (f & 3) << 2;
            float4 a = *(const float4*)(X      + (size_t)(m0 + row) * HIDDEN + k0 + c4);
            sA[c4+0][row] = a.x; sA[c4+1][row] = a.y; sA[c4+2][row] = a.z; sA[c4+3][row] = a.w;
            float4 w = *(const float4*)(g_Weff + (size_t)(n0 + row) * HIDDEN + k0 + c4);
            sB[c4+0][row] = w.x; sB[c4+1][row] = w.y; sB[c4+2][row] = w.z; sB[c4+3][row] = w.w;
        }
        __syncthreads();
#pragma unroll
        for (int k = 0; k < 16; k++) {
            float a[8], bb[8];
            *(float4*)&a[0]  = *(const float4*)&sA[k][ty*8];
            *(float4*)&a[4]  = *(const float4*)&sA[k][ty*8 + 4];
            *(float4*)&bb[0] = *(const float4*)&sB[k][tx*8];
            *(float4*)&bb[4] = *(const float4*)&sB[k][tx*8 + 4];
#pragma unroll
            for (int i = 0; i < 8; i++)
#pragma unroll
                for (int j = 0; j < 8; j++) acc[i][j] += a[i] * bb[j];
        }
        __syncthreads();
    }

#pragma unroll
    for (int i = 0; i < 8; i++) {
        int m = m0 + ty*8 + i;
        int b = m >> 11;          // / SEQ
        int s = m & 2047;
#pragma unroll
        for (int j = 0; j < 8; j++) {
            int n  = n0 + tx*8 + j;
            int p  = n >> 10;
            int hn = n & 1023;
            int h  = hn >> 6;
            int d  = n & 63;
            const float* bias = (p == 0) ? bq : ((p == 1) ? bk : bv);
            g_QKV[(((size_t)p * BH + b*HEADS + h) * SEQ + s) * HD + d] = acc[i][j] + bias[hn];
        }
    }
}

// ---------------------------------------------------------------------------
// Kernel 3: flash attention, fp32.  Block = 128 threads = 128 query rows of one
// (b,h).  Loop over key tiles of 64; K/V tiles in smem (broadcast reads),
// score rows staged in smem with stride 65 (conflict-free STS/LDS).
// ---------------------------------------------------------------------------
#define ATTN_SMEM ((64*64 + 64*64 + 128*65 + 64) * 4)

__global__ __launch_bounds__(128) void attn_kernel(const float* __restrict__ mask,
                                                   float* __restrict__ out) {
    extern __shared__ __align__(16) float smem[];
    float* sK = smem;              // [64][64]
    float* sV = sK + 64*64;        // [64][64]
    float* sS = sV + 64*64;        // [128][65]
    float* sM = sS + 128*65;       // [64]

    int bh = blockIdx.y;
    int b  = bh / HEADS;
    int h  = bh % HEADS;
    int tid = threadIdx.x;
    int q  = blockIdx.x * 128 + tid;

    const float* Qg = g_QKV + ((size_t)bh * SEQ + q) * HD;   // p = 0
    float qreg[HD];
#pragma unroll
    for (int d = 0; d < HD; d += 4) {
        float4 v = *(const float4*)(Qg + d);
        qreg[d] = v.x; qreg[d+1] = v.y; qreg[d+2] = v.z; qreg[d+3] = v.w;
    }

    float mrun = -1e30f, l = 0.f;
    float o[HD];
#pragma unroll
    for (int d = 0; d < HD; d++) o[d] = 0.f;

    const float* maskb = mask + b * SEQ;
    float* srow = sS + tid * 65;

    for (int kt = 0; kt < SEQ; kt += 64) {
        const float4* Kg = (const float4*)(g_QKV + ((size_t)(1*BH + bh) * SEQ + kt) * HD);
        const float4* Vg = (const float4*)(g_QKV + ((size_t)(2*BH + bh) * SEQ + kt) * HD);
#pragma unroll
        for (int it = 0; it < 8; it++) {
            int f = tid + it * 128;              // 1024 float4 = 64*64 floats
            ((float4*)sK)[f] = Kg[f];
            ((float4*)sV)[f] = Vg[f];
        }
        if (tid < 64) sM[tid] = maskb[kt + tid];
        __syncthreads();

        // pass 1: scores for this thread's query row, track tile max
        float tmax = -1e30f;
#pragma unroll 4
        for (int j = 0; j < 64; j++) {
            const float* kr = sK + j * HD;
            float s = 0.f;
#pragma unroll
            for (int d = 0; d < HD; d += 4) {
                float4 kv = *(const float4*)(kr + d);
                s += qreg[d]*kv.x + qreg[d+1]*kv.y + qreg[d+2]*kv.z + qreg[d+3]*kv.w;
            }
            s = s * SM_SCALE + sM[j];
            srow[j] = s;
            tmax = fmaxf(tmax, s);
        }

        // online-softmax rescale
        float mnew = fmaxf(mrun, tmax);
        float corr = __expf(mrun - mnew);
        l *= corr;
#pragma unroll
        for (int d = 0; d < HD; d++) o[d] *= corr;
        mrun = mnew;

        // pass 2: exp + PV accumulate
#pragma unroll 2
        for (int j = 0; j < 64; j++) {
            float p = __expf(srow[j] - mnew);
            l += p;
            const float* vr = sV + j * HD;
#pragma unroll
            for (int d = 0; d < HD; d += 4) {
                float4 vv = *(const float4*)(vr + d);
                o[d]   += p * vv.x; o[d+1] += p * vv.y;
                o[d+2] += p * vv.z; o[d+3] += p * vv.w;
            }
        }
        __syncthreads();
    }

    float inv = 1.f / l;
    float* orow = out + ((size_t)(b * SEQ + q)) * HIDDEN + h * HD;
#pragma unroll
    for (int d = 0; d < HD; d += 4) {
        float4 v = make_float4(o[d]*inv, o[d+1]*inv, o[d+2]*inv, o[d+3]*inv);
        *(float4*)(orow + d) = v;
    }
}

// ---------------------------------------------------------------------------
extern "C" void kernel_launch(void* const* d_in, const int* in_sizes, int n_in,
                              void* d_out, int out_size) {
    const float* X    = (const float*)d_in[0];
    const float* mask = (const float*)d_in[1];
    const float* Wq = (const float*)d_in[2];  const float* bq = (const float*)d_in[3];
    const float* Aq = (const float*)d_in[4];  const float* Bq = (const float*)d_in[5];
    const float* Wk = (const float*)d_in[6];  const float* bk = (const float*)d_in[7];
    const float* Ak = (const float*)d_in[8];  const float* Bk = (const float*)d_in[9];
    const float* Wv = (const float*)d_in[10]; const float* bv = (const float*)d_in[11];
    const float* Av = (const float*)d_in[12]; const float* Bv = (const float*)d_in[13];
    float* out = (float*)d_out;

    // 1. Fold LoRA into dense weights
    weff_kernel<<<(NPROJ*HIDDEN*HIDDEN)/256, 256>>>(Wq, Aq, Bq, Wk, Ak, Bk, Wv, Av, Bv);

    // 2. Fused QKV projection GEMM
    dim3 g2(NPROJ*HIDDEN/128, (BSZ*SEQ)/128);   // (24, 64)
    qkv_gemm<<<g2, 256>>>(X, bq, bk, bv);

    // 3. Flash attention + output transpose (fused)
    cudaFuncSetAttribute(attn_kernel, cudaFuncAttributeMaxDynamicSharedMemorySize, ATTN_SMEM);
    dim3 g3(SEQ/128, BH);                        // (16, 64)
    attn_kernel<<<g3, 128, ATTN_SMEM>>>(mask, out);
}

// round 2
// speedup vs baseline: 2.9074x; 2.9074x over previous
#include <cuda_runtime.h>

#define HIDDEN 1024
#define HEADS 16
#define HD 64
#define RANK 16
#define BSZ 4
#define SEQ 2048
#define BH (BSZ*HEADS)          // 64
#define NPROJ 3
#define LORA_SCALE (1.0f/16.0f)
#define SM_SCALE 0.125f          // 1/sqrt(64)

// Scratch (no allocations allowed)
__device__ float g_Weff[(size_t)NPROJ*HIDDEN*HIDDEN];                 // 12 MB
__device__ float g_QKV[(size_t)NPROJ*BH*SEQ*HD];                      // ~100 MB

// ---------------------------------------------------------------------------
// tf32 helpers
// ---------------------------------------------------------------------------
__device__ __forceinline__ unsigned f2tf(float f) {
    unsigned u;
    asm("cvt.rna.tf32.f32 %0, %1;" : "=r"(u) : "f"(f));
    return u;
}

__device__ __forceinline__ void mma_tf32(float c[4], const unsigned a[4], unsigned b0, unsigned b1) {
    asm volatile(
        "mma.sync.aligned.m16n8k8.row.col.f32.tf32.tf32.f32 "
        "{%0,%1,%2,%3},{%4,%5,%6,%7},{%8,%9},{%0,%1,%2,%3};"
        : "+f"(c[0]), "+f"(c[1]), "+f"(c[2]), "+f"(c[3])
        : "r"(a[0]), "r"(a[1]), "r"(a[2]), "r"(a[3]), "r"(b0), "r"(b1));
}

// ---------------------------------------------------------------------------
// Kernel 1: W_eff = W + (1/16) * B @ A
// ---------------------------------------------------------------------------
__global__ void weff_kernel(const float* __restrict__ Wq, const float* __restrict__ Aq, const float* __restrict__ Bq,
                            const float* __restrict__ Wk, const float* __restrict__ Ak, const float* __restrict__ Bk,
                            const float* __restrict__ Wv, const float* __restrict__ Av, const float* __restrict__ Bv) {
    int idx = blockIdx.x * blockDim.x + threadIdx.x;
    if (idx >= NPROJ*HIDDEN*HIDDEN) return;
    int p  = idx >> 20;
    int nk = idx & ((1 << 20) - 1);
    int n  = nk >> 10;
    int k  = nk & 1023;
    const float* W = (p == 0) ? Wq : ((p == 1) ? Wk : Wv);
    const float* A = (p == 0) ? Aq : ((p == 1) ? Ak : Av);
    const float* B = (p == 0) ? Bq : ((p == 1) ? Bk : Bv);
    float acc = 0.f;
#pragma unroll
    for (int r = 0; r < RANK; r++) acc += B[n*RANK + r] * A[r*HIDDEN + k];
    g_Weff[idx] = W[nk] + LORA_SCALE * acc;
}

// ---------------------------------------------------------------------------
// Kernel 2: QKV GEMM via mma.sync tf32.
// C[m][n] = sum_k X[m][k]*Weff[n][k] + bias[n], M=8192, N=3072, K=1024.
// Block tile 128x128, 8 warps (4 m x 2 n), warp tile 32x64.
// ---------------------------------------------------------------------------
#define KC 32
#define GS 136   // smem stride (floats); (8*tig + g) mod 32 distinct -> conflict-free frags

__global__ __launch_bounds__(256) void qkv_gemm_tf32(const float* __restrict__ X,
                                                     const float* __restrict__ bq,
                                                     const float* __restrict__ bk,
                                                     const float* __restrict__ bv) {
    __shared__ unsigned sA[KC][GS];   // [k][m], tf32 bits
    __shared__ unsigned sB[KC][GS];   // [k][n], tf32 bits
    int tid  = threadIdx.x;
    int lane = tid & 31;
    int wid  = tid >> 5;
    int wm   = wid & 3;        // 0..3 -> 32 rows each
    int wn   = wid >> 2;       // 0..1 -> 64 cols each
    int g    = lane >> 2;
    int tig  = lane & 3;
    int m0 = blockIdx.y * 128;
    int n0 = blockIdx.x * 128;

    float acc[2][8][4];
#pragma unroll
    for (int mt = 0; mt < 2; mt++)
#pragma unroll
        for (int nt = 0; nt < 8; nt++)
#pragma unroll
            for (int i = 0; i < 4; i++) acc[mt][nt][i] = 0.f;

    for (int kc = 0; kc < HIDDEN; kc += KC) {
        // stage: 128 rows x 32 k each, as [k][row], converted to tf32
#pragma unroll
        for (int it = 0; it < 4; it++) {
            int f   = tid + it * 256;       // 0..1023 float4s
            int row = f >> 3;               // 8 float4 per row
            int c4  = (f & 7) << 2;
            float4 a = *(const float4*)(X      + (size_t)(m0 + row) * HIDDEN + kc + c4);
            sA[c4+0][row] = f2tf(a.x); sA[c4+1][row] = f2tf(a.y);
            sA[c4+2][row] = f2tf(a.z); sA[c4+3][row] = f2tf(a.w);
            float4 w = *(const float4*)(g_Weff + (size_t)(n0 + row) * HIDDEN + kc + c4);
            sB[c4+0][row] = f2tf(w.x); sB[c4+1][row] = f2tf(w.y);
            sB[c4+2][row] = f2tf(w.z); sB[c4+3][row] = f2tf(w.w);
        }
        __syncthreads();

#pragma unroll
        for (int ks = 0; ks < KC/8; ks++) {
            int k0 = ks * 8;
            unsigned a[2][4], b[8][2];
#pragma unroll
            for (int mt = 0; mt < 2; mt++) {
                int rb = wm*32 + mt*16;
                a[mt][0] = sA[k0+tig  ][rb+g];
                a[mt][1] = sA[k0+tig  ][rb+g+8];
                a[mt][2] = sA[k0+tig+4][rb+g];
                a[mt][3] = sA[k0+tig+4][rb+g+8];
            }
#pragma unroll
            for (int nt = 0; nt < 8; nt++) {
                int cb = wn*64 + nt*8;
                b[nt][0] = sB[k0+tig  ][cb+g];
                b[nt][1] = sB[k0+tig+4][cb+g];
            }
#pragma unroll
            for (int mt = 0; mt < 2; mt++)
#pragma unroll
                for (int nt = 0; nt < 8; nt++)
                    mma_tf32(acc[mt][nt], a[mt], b[nt][0], b[nt][1]);
        }
        __syncthreads();
    }

    // epilogue: scatter to g_QKV[p][b*16+h][s][d] with bias
#pragma unroll
    for (int mt = 0; mt < 2; mt++) {
#pragma unroll
        for (int half = 0; half < 2; half++) {
            int m = m0 + wm*32 + mt*16 + g + half*8;
            int b = m >> 11;
            int s = m & 2047;
#pragma unroll
            for (int nt = 0; nt < 8; nt++) {
                int n  = n0 + wn*64 + nt*8 + 2*tig;
                int p  = n >> 10;
                int hn = n & 1023;
                int h  = hn >> 6;
                int d  = n & 63;
                const float* bias = (p == 0) ? bq : ((p == 1) ? bk : bv);
                float v0 = acc[mt][nt][half*2 + 0] + bias[hn];
                float v1 = acc[mt][nt][half*2 + 1] + bias[hn + 1];
                float* dst = &g_QKV[(((size_t)p * BH + b*HEADS + h) * SEQ + s) * HD + d];
                *(float2*)dst = make_float2(v0, v1);
            }
        }
    }
}

// ---------------------------------------------------------------------------
// Kernel 3: flash attention via mma.sync tf32.
// Block: 128 threads (4 warps), 64 queries of one (b,h). Key tiles of 64.
// Each warp owns 16 query rows. Q frags in regs; K,V tiles in smem (tf32);
// P staged through per-warp smem region (aliased with Q staging buffer).
// ---------------------------------------------------------------------------
#define SKS 68   // sK/sQ/sP stride: (4g+tig) mod 32 distinct
#define SVS 72   // sV stride:       (8tig+g) mod 32 distinct

#define SMEM_K_WORDS (64*SKS)
#define SMEM_V_WORDS (64*SVS)
#define SMEM_P_WORDS (64*SKS)       // also the Q staging area
#define ATTN_SMEM ((SMEM_K_WORDS + SMEM_V_WORDS + SMEM_P_WORDS + 64) * 4)

__global__ __launch_bounds__(128) void attn_tf32(const float* __restrict__ mask,
                                                 float* __restrict__ out) {
    extern __shared__ __align__(16) unsigned smem[];
    unsigned (*sK)[SKS] = (unsigned (*)[SKS])smem;
    unsigned (*sV)[SVS] = (unsigned (*)[SVS])(smem + SMEM_K_WORDS);
    unsigned* sPbase    = smem + SMEM_K_WORDS + SMEM_V_WORDS;
    float*    sM        = (float*)(sPbase + SMEM_P_WORDS);

    int bh = blockIdx.y;
    int b  = bh >> 4;
    int h  = bh & 15;
    int q0 = blockIdx.x * 64;
    int tid  = threadIdx.x;
    int w    = tid >> 5;
    int lane = tid & 31;
    int g    = lane >> 2;
    int tig  = lane & 3;

    // ---- stage Q tile (64x64) into sP area as tf32, then load A-fragments ----
    unsigned (*sQ)[SKS] = (unsigned (*)[SKS])sPbase;
    {
        const float* Qg = g_QKV + ((size_t)bh * SEQ + q0) * HD;
#pragma unroll
        for (int it = 0; it < 8; it++) {
            int f   = tid + it * 128;     // 1024 float4s
            int row = f >> 4;
            int c4  = (f & 15) << 2;
            float4 v = *(const float4*)(Qg + row * HD + c4);
            sQ[row][c4+0] = f2tf(v.x); sQ[row][c4+1] = f2tf(v.y);
            sQ[row][c4+2] = f2tf(v.z); sQ[row][c4+3] = f2tf(v.w);
        }
    }
    __syncthreads();

    unsigned qa[8][4];
    int qb = w * 16;
#pragma unroll
    for (int kt = 0; kt < 8; kt++) {
        qa[kt][0] = sQ[qb+g  ][kt*8+tig];
        qa[kt][1] = sQ[qb+g+8][kt*8+tig];
        qa[kt][2] = sQ[qb+g  ][kt*8+tig+4];
        qa[kt][3] = sQ[qb+g+8][kt*8+tig+4];
    }
    __syncthreads();   // everyone has Q frags; sP region now reusable

    unsigned (*sPw)[SKS] = (unsigned (*)[SKS])(sPbase + w * 16 * SKS);

    float o[8][4];
#pragma unroll
    for (int nt = 0; nt < 8; nt++)
#pragma unroll
        for (int i = 0; i < 4; i++) o[nt][i] = 0.f;
    float mlo = -1e30f, mhi = -1e30f, llo = 0.f, lhi = 0.f;

    const float* maskb = mask + b * SEQ;

    for (int kt0 = 0; kt0 < SEQ; kt0 += 64) {
        // ---- stage K and V tiles (tf32) + mask ----
        const float* Kg = g_QKV + ((size_t)(BH   + bh) * SEQ + kt0) * HD;
        const float* Vg = g_QKV + ((size_t)(2*BH + bh) * SEQ + kt0) * HD;
#pragma unroll
        for (int it = 0; it < 8; it++) {
            int f   = tid + it * 128;
            int row = f >> 4;
            int c4  = (f & 15) << 2;
            float4 kv = *(const float4*)(Kg + row * HD + c4);
            sK[row][c4+0] = f2tf(kv.x); sK[row][c4+1] = f2tf(kv.y);
            sK[row][c4+2] = f2tf(kv.z); sK[row][c4+3] = f2tf(kv.w);
            float4 vv = *(const float4*)(Vg + row * HD + c4);
            sV[row][c4+0] = f2tf(vv.x); sV[row][c4+1] = f2tf(vv.y);
            sV[row][c4+2] = f2tf(vv.z); sV[row][c4+3] = f2tf(vv.w);
        }
        if (tid < 64) sM[tid] = maskb[kt0 + tid];
        __syncthreads();

        // ---- S = Q K^T (16x64 per warp) ----
        float s[8][4];
#pragma unroll
        for (int nt = 0; nt < 8; nt++) {
            s[nt][0] = s[nt][1] = s[nt][2] = s[nt][3] = 0.f;
#pragma unroll
            for (int kt = 0; kt < 8; kt++) {
                unsigned b0 = sK[nt*8+g][kt*8+tig];
                unsigned b1 = sK[nt*8+g][kt*8+tig+4];
                mma_tf32(s[nt], qa[kt], b0, b1);
            }
        }

        // ---- scale + mask + tile max ----
        float tml = -1e30f, tmh = -1e30f;
#pragma unroll
        for (int nt = 0; nt < 8; nt++) {
            int c = nt*8 + 2*tig;
            float m0v = sM[c], m1v = sM[c+1];
            s[nt][0] = s[nt][0] * SM_SCALE + m0v;
            s[nt][1] = s[nt][1] * SM_SCALE + m1v;
            s[nt][2] = s[nt][2] * SM_SCALE + m0v;
            s[nt][3] = s[nt][3] * SM_SCALE + m1v;
            tml = fmaxf(tml, fmaxf(s[nt][0], s[nt][1]));
            tmh = fmaxf(tmh, fmaxf(s[nt][2], s[nt][3]));
        }
        tml = fmaxf(tml, __shfl_xor_sync(0xffffffff, tml, 1));
        tml = fmaxf(tml, __shfl_xor_sync(0xffffffff, tml, 2));
        tmh = fmaxf(tmh, __shfl_xor_sync(0xffffffff, tmh, 1));
        tmh = fmaxf(tmh, __shfl_xor_sync(0xffffffff, tmh, 2));

        float mnl = fmaxf(mlo, tml), mnh = fmaxf(mhi, tmh);
        float cl = __expf(mlo - mnl), ch = __expf(mhi - mnh);
        llo *= cl; lhi *= ch;
        mlo = mnl; mhi = mnh;
#pragma unroll
        for (int nt = 0; nt < 8; nt++) {
            o[nt][0] *= cl; o[nt][1] *= cl;
            o[nt][2] *= ch; o[nt][3] *= ch;
        }

        // ---- exp + partial row sums + stage P (tf32) ----
#pragma unroll
        for (int nt = 0; nt < 8; nt++) {
            float p0 = __expf(s[nt][0] - mnl);
            float p1 = __expf(s[nt][1] - mnl);
            float p2 = __expf(s[nt][2] - mnh);
            float p3 = __expf(s[nt][3] - mnh);
            llo += p0 + p1; lhi += p2 + p3;
            int c = nt*8 + 2*tig;
            *(uint2*)&sPw[g  ][c] = make_uint2(f2tf(p0), f2tf(p1));
            *(uint2*)&sPw[g+8][c] = make_uint2(f2tf(p2), f2tf(p3));
        }
        __syncwarp();

        // ---- O += P V ----
        unsigned pa[8][4];
#pragma unroll
        for (int kt = 0; kt < 8; kt++) {
            pa[kt][0] = sPw[g  ][kt*8+tig];
            pa[kt][1] = sPw[g+8][kt*8+tig];
            pa[kt][2] = sPw[g  ][kt*8+tig+4];
            pa[kt][3] = sPw[g+8][kt*8+tig+4];
        }
#pragma unroll
        for (int nt = 0; nt < 8; nt++) {
#pragma unroll
            for (int kt = 0; kt < 8; kt++) {
                unsigned b0 = sV[kt*8+tig  ][nt*8+g];
                unsigned b1 = sV[kt*8+tig+4][nt*8+g];
                mma_tf32(o[nt], pa[kt], b0, b1);
            }
        }
        __syncthreads();
    }

    // ---- finalize: full row sums, normalize, write out[b][s][h*64+d] ----
    llo += __shfl_xor_sync(0xffffffff, llo, 1);
    llo += __shfl_xor_sync(0xffffffff, llo, 2);
    lhi += __shfl_xor_sync(0xffffffff, lhi, 1);
    lhi += __shfl_xor_sync(0xffffffff, lhi, 2);
    float invl = 1.f / llo, invh = 1.f / lhi;

    int row_lo = q0 + qb + g;
    int row_hi = row_lo + 8;
    float* out_lo = out + ((size_t)(b * SEQ + row_lo)) * HIDDEN + h * HD;
    float* out_hi = out + ((size_t)(b * SEQ + row_hi)) * HIDDEN + h * HD;
#pragma unroll
    for (int nt = 0; nt < 8; nt++) {
        int d = nt*8 + 2*tig;
        *(float2*)(out_lo + d) = make_float2(o[nt][0] * invl, o[nt][1] * invl);
        *(float2*)(out_hi + d) = make_float2(o[nt][2] * invh, o[nt][3] * invh);
    }
}

// ---------------------------------------------------------------------------
extern "C" void kernel_launch(void* const* d_in, const int* in_sizes, int n_in,
                              void* d_out, int out_size) {
    const float* X    = (const float*)d_in[0];
    const float* mask = (const float*)d_in[1];
    const float* Wq = (const float*)d_in[2];  const float* bq = (const float*)d_in[3];
    const float* Aq = (const float*)d_in[4];  const float* Bq = (const float*)d_in[5];
    const float* Wk = (const float*)d_in[6];  const float* bk = (const float*)d_in[7];
    const float* Ak = (const float*)d_in[8];  const float* Bk = (const float*)d_in[9];
    const float* Wv = (const float*)d_in[10]; const float* bv = (const float*)d_in[11];
    const float* Av = (const float*)d_in[12]; const float* Bv = (const float*)d_in[13];
    float* out = (float*)d_out;

    weff_kernel<<<(NPROJ*HIDDEN*HIDDEN)/256, 256>>>(Wq, Aq, Bq, Wk, Ak, Bk, Wv, Av, Bv);

    dim3 g2(NPROJ*HIDDEN/128, (BSZ*SEQ)/128);   // (24, 64)
    qkv_gemm_tf32<<<g2, 256>>>(X, bq, bk, bv);

    cudaFuncSetAttribute(attn_tf32, cudaFuncAttributeMaxDynamicSharedMemorySize, ATTN_SMEM);
    dim3 g3(SEQ/64, BH);                         // (32, 64)
    attn_tf32<<<g3, 128, ATTN_SMEM>>>(mask, out);
}

// round 3
// speedup vs baseline: 4.2452x; 1.4601x over previous
#include <cuda_runtime.h>

#define HIDDEN 1024
#define HEADS 16
#define HD 64
#define RANK 16
#define BSZ 4
#define SEQ 2048
#define BH (BSZ*HEADS)          // 64
#define NPROJ 3
#define LORA_SCALE (1.0f/16.0f)
#define SM_SCALE 0.125f          // 1/sqrt(64)

// Scratch (no allocations allowed)
__device__ float g_Weff[(size_t)NPROJ*HIDDEN*HIDDEN];   // tf32-rounded bits
__device__ float g_Xtf [(size_t)BSZ*SEQ*HIDDEN];        // tf32-rounded X
__device__ float g_QKV [(size_t)NPROJ*BH*SEQ*HD];       // tf32-rounded Q,K,V

// ---------------------------------------------------------------------------
// helpers
// ---------------------------------------------------------------------------
__device__ __forceinline__ unsigned f2tf(float f) {
    unsigned u;
    asm("cvt.rna.tf32.f32 %0, %1;" : "=r"(u) : "f"(f));
    return u;
}
__device__ __forceinline__ float f2tf_f(float f) {
    return __uint_as_float(f2tf(f));
}
__device__ __forceinline__ void mma_tf32(float c[4], const unsigned a[4], unsigned b0, unsigned b1) {
    asm volatile(
        "mma.sync.aligned.m16n8k8.row.col.f32.tf32.tf32.f32 "
        "{%0,%1,%2,%3},{%4,%5,%6,%7},{%8,%9},{%0,%1,%2,%3};"
        : "+f"(c[0]), "+f"(c[1]), "+f"(c[2]), "+f"(c[3])
        : "r"(a[0]), "r"(a[1]), "r"(a[2]), "r"(a[3]), "r"(b0), "r"(b1));
}
__device__ __forceinline__ void cpa16(float* dst, const float* src) {
    unsigned a = (unsigned)__cvta_generic_to_shared(dst);
    asm volatile("cp.async.cg.shared.global [%0], [%1], 16;" :: "r"(a), "l"(src));
}
__device__ __forceinline__ void cpa16v(volatile float* dst, const float* src) {
    unsigned a = (unsigned)__cvta_generic_to_shared((void*)dst);
    asm volatile("cp.async.cg.shared.global [%0], [%1], 16;" :: "r"(a), "l"(src));
}
#define CP_COMMIT asm volatile("cp.async.commit_group;")
#define CP_WAIT0  asm volatile("cp.async.wait_group 0;")
#define CP_WAIT1  asm volatile("cp.async.wait_group 1;")

// ---------------------------------------------------------------------------
// Kernel 1a: W_eff = tf32(W + (1/16) * B @ A)
// ---------------------------------------------------------------------------
__global__ void weff_kernel(const float* __restrict__ Wq, const float* __restrict__ Aq, const float* __restrict__ Bq,
                            const float* __restrict__ Wk, const float* __restrict__ Ak, const float* __restrict__ Bk,
                            const float* __restrict__ Wv, const float* __restrict__ Av, const float* __restrict__ Bv) {
    int idx = blockIdx.x * blockDim.x + threadIdx.x;
    if (idx >= NPROJ*HIDDEN*HIDDEN) return;
    int p  = idx >> 20;
    int nk = idx & ((1 << 20) - 1);
    int n  = nk >> 10;
    int k  = nk & 1023;
    const float* W = (p == 0) ? Wq : ((p == 1) ? Wk : Wv);
    const float* A = (p == 0) ? Aq : ((p == 1) ? Ak : Av);
    const float* B = (p == 0) ? Bq : ((p == 1) ? Bk : Bv);
    float acc = 0.f;
#pragma unroll
    for (int r = 0; r < RANK; r++) acc += B[n*RANK + r] * A[r*HIDDEN + k];
    g_Weff[idx] = f2tf_f(W[nk] + LORA_SCALE * acc);
}

// ---------------------------------------------------------------------------
// Kernel 1b: X -> tf32
// ---------------------------------------------------------------------------
__global__ void xtf_kernel(const float* __restrict__ X) {
    int i = blockIdx.x * blockDim.x + threadIdx.x;     // float4 index
    float4 v = ((const float4*)X)[i];
    float4 o = make_float4(f2tf_f(v.x), f2tf_f(v.y), f2tf_f(v.z), f2tf_f(v.w));
    ((float4*)g_Xtf)[i] = o;
}

// ---------------------------------------------------------------------------
// Kernel 2: QKV GEMM, mma tf32, cp.async 2-stage pipeline.
// Block tile 128x128, K-slab 32.  Smem row-major, stride 36 (conflict-free).
// ---------------------------------------------------------------------------
#define GST 36
#define SAB (128*GST)

__global__ __launch_bounds__(256) void qkv_gemm_tf32(const float* __restrict__ bq,
                                                     const float* __restrict__ bk,
                                                     const float* __restrict__ bv) {
    extern __shared__ __align__(16) float gsm[];
    int tid  = threadIdx.x;
    int lane = tid & 31;
    int wid  = tid >> 5;
    int wm   = wid & 3;
    int wn   = wid >> 2;
    int g    = lane >> 2;
    int tig  = lane & 3;
    int m0 = blockIdx.y * 128;
    int n0 = blockIdx.x * 128;

    float acc[2][8][4];
#pragma unroll
    for (int mt = 0; mt < 2; mt++)
#pragma unroll
        for (int nt = 0; nt < 8; nt++)
#pragma unroll
            for (int i = 0; i < 4; i++) acc[mt][nt][i] = 0.f;

    int frow = tid >> 3;
    int fc4  = (tid & 7) << 2;

    // issue one K-slab into buffer
#define ISSUE(slab, buf) do {                                                     \
        float* sA_ = gsm + (buf)*2*SAB;                                           \
        float* sB_ = sA_ + SAB;                                                   \
        int kc_ = (slab)*32;                                                      \
        _Pragma("unroll")                                                         \
        for (int it = 0; it < 4; it++) {                                          \
            int row = frow + it*32;                                               \
            cpa16(sA_ + row*GST + fc4, g_Xtf  + (size_t)(m0+row)*HIDDEN + kc_ + fc4); \
            cpa16(sB_ + row*GST + fc4, g_Weff + (size_t)(n0+row)*HIDDEN + kc_ + fc4); \
        }                                                                         \
        CP_COMMIT;                                                                \
    } while (0)

    ISSUE(0, 0);

    for (int s = 0; s < HIDDEN/32; s++) {
        if (s + 1 < HIDDEN/32) { ISSUE(s+1, (s+1)&1); CP_WAIT1; }
        else                   { CP_WAIT0; }
        __syncthreads();

        const unsigned* uA = (const unsigned*)(gsm + (s&1)*2*SAB);
        const unsigned* uB = uA + SAB;
#pragma unroll
        for (int ks = 0; ks < 4; ks++) {
            int k0 = ks * 8;
            unsigned a[2][4], b[8][2];
#pragma unroll
            for (int mt = 0; mt < 2; mt++) {
                int rb = wm*32 + mt*16;
                a[mt][0] = uA[(rb+g  )*GST + k0+tig  ];
                a[mt][1] = uA[(rb+g+8)*GST + k0+tig  ];
                a[mt][2] = uA[(rb+g  )*GST + k0+tig+4];
                a[mt][3] = uA[(rb+g+8)*GST + k0+tig+4];
            }
#pragma unroll
            for (int nt = 0; nt < 8; nt++) {
                int cb = wn*64 + nt*8;
                b[nt][0] = uB[(cb+g)*GST + k0+tig  ];
                b[nt][1] = uB[(cb+g)*GST + k0+tig+4];
            }
#pragma unroll
            for (int mt = 0; mt < 2; mt++)
#pragma unroll
                for (int nt = 0; nt < 8; nt++)
                    mma_tf32(acc[mt][nt], a[mt], b[nt][0], b[nt][1]);
        }
        __syncthreads();
    }

    // epilogue: bias + tf32-round, scatter to g_QKV[p][bh][s][d]
#pragma unroll
    for (int mt = 0; mt < 2; mt++) {
#pragma unroll
        for (int half = 0; half < 2; half++) {
            int m = m0 + wm*32 + mt*16 + g + half*8;
            int b = m >> 11;
            int sq = m & 2047;
#pragma unroll
            for (int nt = 0; nt < 8; nt++) {
                int n  = n0 + wn*64 + nt*8 + 2*tig;
                int p  = n >> 10;
                int hn = n & 1023;
                int h  = hn >> 6;
                int d  = n & 63;
                const float* bias = (p == 0) ? bq : ((p == 1) ? bk : bv);
                float v0 = f2tf_f(acc[mt][nt][half*2 + 0] + bias[hn]);
                float v1 = f2tf_f(acc[mt][nt][half*2 + 1] + bias[hn + 1]);
                float* dst = &g_QKV[(((size_t)p * BH + b*HEADS + h) * SEQ + sq) * HD + d];
                *(float2*)dst = make_float2(v0, v1);
            }
        }
    }
}

// ---------------------------------------------------------------------------
// Kernel 3: flash attention, mma tf32, cp.async staging (K/V/Q pre-rounded).
// 128 threads / 64 queries; key tiles of 64.
// ---------------------------------------------------------------------------
#define SKS 68   // sK/sQ/sP stride
#define SVS 72   // sV stride
#define SMEM_K_WORDS (64*SKS)
#define SMEM_V_WORDS (64*SVS)
#define SMEM_P_WORDS (64*SKS)
#define ATTN_SMEM ((SMEM_K_WORDS + SMEM_V_WORDS + SMEM_P_WORDS + 64) * 4)

__global__ __launch_bounds__(128) void attn_tf32(const float* __restrict__ mask,
                                                 float* __restrict__ out) {
    extern __shared__ __align__(16) float asm_[];
    float* sK     = asm_;
    float* sV     = sK + SMEM_K_WORDS;
    float* sPbase = sV + SMEM_V_WORDS;
    float* sM     = sPbase + SMEM_P_WORDS;

    int bh = blockIdx.y;
    int b  = bh >> 4;
    int h  = bh & 15;
    int q0 = blockIdx.x * 64;
    int tid  = threadIdx.x;
    int w    = tid >> 5;
    int lane = tid & 31;
    int g    = lane >> 2;
    int tig  = lane & 3;

    int frow = tid >> 1;              // 128 threads -> 64 rows, 2 thr/row
    int fc4  = (tid & 1) << 5;        // two 32-float halves... (we use 8 f4/row, see loop)

    // ---- stage Q tile (already tf32 bits) into sP region via cp.async ----
    {
        const float* Qg = g_QKV + ((size_t)bh * SEQ + q0) * HD;
#pragma unroll
        for (int it = 0; it < 8; it++) {
            int f   = tid + it * 128;          // 1024 float4s
            int row = f >> 4;
            int c4  = (f & 15) << 2;
            cpa16(sPbase + row*SKS + c4, Qg + row*HD + c4);
        }
        CP_COMMIT; CP_WAIT0;
    }
    __syncthreads();

    unsigned qa[8][4];
    int qb = w * 16;
    {
        const unsigned* uQ = (const unsigned*)sPbase;
#pragma unroll
        for (int kt = 0; kt < 8; kt++) {
            qa[kt][0] = uQ[(qb+g  )*SKS + kt*8+tig  ];
            qa[kt][1] = uQ[(qb+g+8)*SKS + kt*8+tig  ];
            qa[kt][2] = uQ[(qb+g  )*SKS + kt*8+tig+4];
            qa[kt][3] = uQ[(qb+g+8)*SKS + kt*8+tig+4];
        }
    }
    __syncthreads();   // sP region reusable

    unsigned* sPw = (unsigned*)(sPbase + w * 16 * SKS);

    float o[8][4];
#pragma unroll
    for (int nt = 0; nt < 8; nt++)
#pragma unroll
        for (int i = 0; i < 4; i++) o[nt][i] = 0.f;
    float mlo = -1e30f, mhi = -1e30f, llo = 0.f, lhi = 0.f;

    const float* maskb = mask + b * SEQ;

    for (int kt0 = 0; kt0 < SEQ; kt0 += 64) {
        // ---- stage K, V, mask via cp.async ----
        const float* Kg = g_QKV + ((size_t)(BH   + bh) * SEQ + kt0) * HD;
        const float* Vg = g_QKV + ((size_t)(2*BH + bh) * SEQ + kt0) * HD;
#pragma unroll
        for (int it = 0; it < 8; it++) {
            int f   = tid + it * 128;
            int row = f >> 4;
            int c4  = (f & 15) << 2;
            cpa16(sK + row*SKS + c4, Kg + row*HD + c4);
            cpa16(sV + row*SVS + c4, Vg + row*HD + c4);
        }
        if (tid < 16) cpa16(sM + tid*4, maskb + kt0 + tid*4);
        CP_COMMIT; CP_WAIT0;
        __syncthreads();

        const unsigned* uK = (const unsigned*)sK;
        const unsigned* uV = (const unsigned*)sV;

        // ---- S = Q K^T ----
        float s[8][4];
#pragma unroll
        for (int nt = 0; nt < 8; nt++) {
            s[nt][0] = s[nt][1] = s[nt][2] = s[nt][3] = 0.f;
#pragma unroll
            for (int kt = 0; kt < 8; kt++) {
                unsigned b0 = uK[(nt*8+g)*SKS + kt*8+tig  ];
                unsigned b1 = uK[(nt*8+g)*SKS + kt*8+tig+4];
                mma_tf32(s[nt], qa[kt], b0, b1);
            }
        }

        // ---- scale + mask + tile max ----
        float tml = -1e30f, tmh = -1e30f;
#pragma unroll
        for (int nt = 0; nt < 8; nt++) {
            int c = nt*8 + 2*tig;
            float m0v = sM[c], m1v = sM[c+1];
            s[nt][0] = s[nt][0] * SM_SCALE + m0v;
            s[nt][1] = s[nt][1] * SM_SCALE + m1v;
            s[nt][2] = s[nt][2] * SM_SCALE + m0v;
            s[nt][3] = s[nt][3] * SM_SCALE + m1v;
            tml = fmaxf(tml, fmaxf(s[nt][0], s[nt][1]));
            tmh = fmaxf(tmh, fmaxf(s[nt][2], s[nt][3]));
        }
        tml = fmaxf(tml, __shfl_xor_sync(0xffffffff, tml, 1));
        tml = fmaxf(tml, __shfl_xor_sync(0xffffffff, tml, 2));
        tmh = fmaxf(tmh, __shfl_xor_sync(0xffffffff, tmh, 1));
        tmh = fmaxf(tmh, __shfl_xor_sync(0xffffffff, tmh, 2));

        float mnl = fmaxf(mlo, tml), mnh = fmaxf(mhi, tmh);
        float cl = __expf(mlo - mnl), ch = __expf(mhi - mnh);
        llo *= cl; lhi *= ch;
        mlo = mnl; mhi = mnh;
#pragma unroll
        for (int nt = 0; nt < 8; nt++) {
            o[nt][0] *= cl; o[nt][1] *= cl;
            o[nt][2] *= ch; o[nt][3] *= ch;
        }

        // ---- exp + partial sums + stage P (tf32) ----
#pragma unroll
        for (int nt = 0; nt < 8; nt++) {
            float p0 = __expf(s[nt][0] - mnl);
            float p1 = __expf(s[nt][1] - mnl);
            float p2 = __expf(s[nt][2] - mnh);
            float p3 = __expf(s[nt][3] - mnh);
            llo += p0 + p1; lhi += p2 + p3;
            int c = nt*8 + 2*tig;
            *(uint2*)&sPw[(g  )*SKS + c] = make_uint2(f2tf(p0), f2tf(p1));
            *(uint2*)&sPw[(g+8)*SKS + c] = make_uint2(f2tf(p2), f2tf(p3));
        }
        __syncwarp();

        // ---- O += P V ----
        unsigned pa[8][4];
#pragma unroll
        for (int kt = 0; kt < 8; kt++) {
            pa[kt][0] = sPw[(g  )*SKS + kt*8+tig  ];
            pa[kt][1] = sPw[(g+8)*SKS + kt*8+tig  ];
            pa[kt][2] = sPw[(g  )*SKS + kt*8+tig+4];
            pa[kt][3] = sPw[(g+8)*SKS + kt*8+tig+4];
        }
#pragma unroll
        for (int nt = 0; nt < 8; nt++) {
#pragma unroll
            for (int kt = 0; kt < 8; kt++) {
                unsigned b0 = uV[(kt*8+tig  )*SVS + nt*8+g];
                unsigned b1 = uV[(kt*8+tig+4)*SVS + nt*8+g];
                mma_tf32(o[nt], pa[kt], b0, b1);
            }
        }
        __syncthreads();
    }

    // ---- finalize ----
    llo += __shfl_xor_sync(0xffffffff, llo, 1);
    llo += __shfl_xor_sync(0xffffffff, llo, 2);
    lhi += __shfl_xor_sync(0xffffffff, lhi, 1);
    lhi += __shfl_xor_sync(0xffffffff, lhi, 2);
    float invl = 1.f / llo, invh = 1.f / lhi;

    int row_lo = q0 + qb + g;
    int row_hi = row_lo + 8;
    float* out_lo = out + ((size_t)(b * SEQ + row_lo)) * HIDDEN + h * HD;
    float* out_hi = out + ((size_t)(b * SEQ + row_hi)) * HIDDEN + h * HD;
#pragma unroll
    for (int nt = 0; nt < 8; nt++) {
        int d = nt*8 + 2*tig;
        *(float2*)(out_lo + d) = make_float2(o[nt][0] * invl, o[nt][1] * invl);
        *(float2*)(out_hi + d) = make_float2(o[nt][2] * invh, o[nt][3] * invh);
    }
}

// ---------------------------------------------------------------------------
extern "C" void kernel_launch(void* const* d_in, const int* in_sizes, int n_in,
                              void* d_out, int out_size) {
    const float* X    = (const float*)d_in[0];
    const float* mask = (const float*)d_in[1];
    const float* Wq = (const float*)d_in[2];  const float* bq = (const float*)d_in[3];
    const float* Aq = (const float*)d_in[4];  const float* Bq = (const float*)d_in[5];
    const float* Wk = (const float*)d_in[6];  const float* bk = (const float*)d_in[7];
    const float* Ak = (const float*)d_in[8];  const float* Bk = (const float*)d_in[9];
    const float* Wv = (const float*)d_in[10]; const float* bv = (const float*)d_in[11];
    const float* Av = (const float*)d_in[12]; const float* Bv = (const float*)d_in[13];
    float* out = (float*)d_out;

    weff_kernel<<<(NPROJ*HIDDEN*HIDDEN)/256, 256>>>(Wq, Aq, Bq, Wk, Ak, Bk, Wv, Av, Bv);
    xtf_kernel<<<(BSZ*SEQ*HIDDEN/4)/256, 256>>>(X);

    static bool attr_done = false;
    if (!attr_done) {
        cudaFuncSetAttribute(qkv_gemm_tf32, cudaFuncAttributeMaxDynamicSharedMemorySize, 4*2*2*SAB);
        cudaFuncSetAttribute(attn_tf32,     cudaFuncAttributeMaxDynamicSharedMemorySize, ATTN_SMEM);
        attr_done = true;
    }

    dim3 g2(NPROJ*HIDDEN/128, (BSZ*SEQ)/128);   // (24, 64)
    qkv_gemm_tf32<<<g2, 256, 2*2*SAB*4>>>(bq, bk, bv);

    dim3 g3(SEQ/64, BH);                         // (32, 64)
    attn_tf32<<<g3, 128, ATTN_SMEM>>>(mask, out);
}